// round 16
// baseline (speedup 1.0000x reference)
#include <cuda_runtime.h>
#include <math.h>
#include <stdint.h>

// ---------------- problem constants ----------------
constexpr int HI = 256, WI = 256, HL = 64, WL = 64;
constexpr int MB  = 4096;     // m-blocks of 128 rows
constexpr int CH  = 256;      // m-blocks per chunk
constexpr int NTH = 256;
constexpr int NT  = 16;       // 8-col n-tiles per CTA -> 128 cols/CTA

// L1: K=448(386 pad), KC=7,  N=1024, NB=8
// L2: K=1024,         KC=16, N=512,  NB=4
// L3: K=512,          KC=8,  N=256,  NB=2
// L4: K=256,          KC=4,  N=128,  NB=1

#define DEVINL __device__ __forceinline__

// activation digit images: [mb][plane(hi/lo)][row(128)][K bytes]  (u32-packed)
__device__ uint32_t X0I[(size_t)CH * 2 * 128 * 112];
__device__ uint32_t X1I[(size_t)CH * 2 * 128 * 256];
__device__ uint32_t X2I[(size_t)CH * 2 * 128 * 128];
__device__ uint32_t X3I[(size_t)CH * 2 * 128 * 64];
// activation row scales: [mb][group][row]
__device__ float X0S[CH * 4 * 128];
__device__ float X1S[CH * 8 * 128];
__device__ float X2S[CH * 4 * 128];
__device__ float X3S[CH * 2 * 128];
// weight digit blobs: [nb][kc][nt][tile(2)][lane(32)] uint4 = (hi_b0,hi_b1,lo_b0,lo_b1)
__device__ uint4 W1B[8 * 7  * NT * 2 * 32];
__device__ uint4 W2B[4 * 16 * NT * 2 * 32];
__device__ uint4 W3B[2 * 8  * NT * 2 * 32];
__device__ uint4 W4B[1 * 4  * NT * 2 * 32];
// weight column scales
__device__ float W1S[1024], W2S[512], W3S[256], W4S[128];

// ---------------- helpers ----------------
DEVINL void mma_s8(int* d, const uint32_t* a, uint32_t b0, uint32_t b1) {
    asm("mma.sync.aligned.m16n8k32.row.col.s32.s8.s8.s32 "
        "{%0,%1,%2,%3}, {%4,%5,%6,%7}, {%8,%9}, {%0,%1,%2,%3};"
        : "+r"(d[0]), "+r"(d[1]), "+r"(d[2]), "+r"(d[3])
        : "r"(a[0]), "r"(a[1]), "r"(a[2]), "r"(a[3]), "r"(b0), "r"(b1));
}
DEVINL uint32_t smem_u32(const void* p) {
    uint32_t a;
    asm("{ .reg .u64 t; cvta.to.shared.u64 t, %1; cvt.u32.u64 %0, t; }" : "=r"(a) : "l"(p));
    return a;
}
DEVINL void cpa16(uint32_t s, const void* g) {
    asm volatile("cp.async.cg.shared.global [%0], [%1], 16;" :: "r"(s), "l"(g) : "memory");
}
DEVINL void cpa_commit() { asm volatile("cp.async.commit_group;" ::: "memory"); }
template<int N> DEVINL void cpa_wait() { asm volatile("cp.async.wait_group %0;" :: "n"(N) : "memory"); }

DEVINL void qdig(float v, float inv, int& x1, int& x0) {
    int X = __float2int_rn(v * inv);     // |X| <= 32512
    x1 = (X + 128) >> 8;                 // [-127,127]
    x0 = X - (x1 << 8);                  // [-128,127]
}

// ---------------- weight prep ----------------
__global__ void colmax_k(const float* __restrict__ W, int K, int N, float* __restrict__ S) {
    int n = blockIdx.x * blockDim.x + threadIdx.x;
    if (n >= N) return;
    float m = 0.f;
    for (int k = 0; k < K; ++k) m = fmaxf(m, fabsf(W[(size_t)k * N + n]));
    S[n] = (m > 0.f) ? m / 32512.f : 1.f;
}

__global__ void prep_w(const float* __restrict__ W, const float* __restrict__ S,
                       int K, int N, int NB, int KC, int sel) {
    uint4* dst = (sel == 1) ? W1B : (sel == 2) ? W2B : (sel == 3) ? W3B : W4B;
    int total = NB * KC * NT * 2 * 32;
    int idx = blockIdx.x * blockDim.x + threadIdx.x;
    if (idx >= total) return;
    int lane = idx & 31; int t = idx >> 5;
    int tile = t & 1; t >>= 1;
    int nt = t % NT; t /= NT;
    int kc = t % KC; int nbb = t / KC;
    int cg = lane >> 2, t4 = lane & 3;
    int n = nbb * 128 + nt * 8 + cg;
    float inv = 1.f / S[n];
    uint32_t c[4] = {0, 0, 0, 0};
    #pragma unroll
    for (int i = 0; i < 2; ++i)
        #pragma unroll
        for (int b = 0; b < 4; ++b) {
            int k = kc * 64 + tile * 32 + i * 16 + t4 * 4 + b;
            float v = (k < K) ? W[(size_t)k * N + n] : 0.f;
            int x1, x0; qdig(v, inv, x1, x0);
            c[i]     |= ((uint32_t)(uint8_t)(int8_t)x1) << (8 * b);
            c[2 + i] |= ((uint32_t)(uint8_t)(int8_t)x0) << (8 * b);
        }
    dst[idx] = make_uint4(c[0], c[1], c[2], c[3]);
}

// ---------------- gather: build X0 digit image + row scales ----------------
__global__ __launch_bounds__(NTH, 1)
void gather_k(const float* __restrict__ feat, const float* __restrict__ coord,
              const float* __restrict__ hr, const float* __restrict__ lr, int mb0)
{
    const int tid = threadIdx.x, lane = tid & 31, warp = tid >> 5;
    const int mb = blockIdx.x;

    for (int rr = 0; rr < 16; ++rr) {
        int row = warp * 16 + rr;
        int grow = (mb0 + mb) * 128 + row;
        int p = grow >> 2, br = grow & 3, b = p >> 16;

        float y = coord[(size_t)p * 2 + 0];
        float x = coord[(size_t)p * 2 + 1];

        int ihy = (int)floorf((y + 1.0f) * (0.5f * HI));
        int ihx = (int)floorf((x + 1.0f) * (0.5f * WI));
        bool vh = (ihy >= 0) & (ihy < HI) & (ihx >= 0) & (ihx < WI);
        int ihyc = min(max(ihy, 0), HI - 1);
        int ihxc = min(max(ihx, 0), WI - 1);

        float vx = (br & 2) ? 1.0f : -1.0f;
        float vy = (br & 1) ? 1.0f : -1.0f;
        float cy = y + vx * (1.0f / (float)HL);
        float cx = x + vy * (1.0f / (float)WL);
        int iy = (int)floorf((cy + 1.0f) * (0.5f * HL));
        int ix = (int)floorf((cx + 1.0f) * (0.5f * WL));
        bool v = (iy >= 0) & (iy < HL) & (ix >= 0) & (ix < WL);
        int iyc = min(max(iy, 0), HL - 1);
        int ixc = min(max(ix, 0), WL - 1);

        float qy = v ? (-1.0f + (2 * iyc + 1) * (1.0f / (float)HL)) : 0.0f;
        float qx = v ? (-1.0f + (2 * ixc + 1) * (1.0f / (float)WL)) : 0.0f;
        float rel_y = (y - qy) * (float)HL;
        float rel_x = (x - qx) * (float)WL;

        const float* featb = feat + (size_t)b * 128 * 4096;
        const float* hrb   = hr   + (size_t)b * 128 * 65536;
        const float* lrb   = lr   + (size_t)b * 128 * 4096;
        int fidx = iyc * WL + ixc;
        int hidx = ihyc * WI + ihxc;

        float vals[4][4];
        float vmax = 0.f;
        #pragma unroll
        for (int j = 0; j < 4; ++j) {
            int c = lane + 32 * j;
            #pragma unroll
            for (int bb = 0; bb < 4; ++bb) vals[j][bb] = 0.f;
            if (c < 112) {
                int kb = 4 * c;
                if (kb < 128) {
                    if (v)
                        #pragma unroll
                        for (int bb = 0; bb < 4; ++bb) vals[j][bb] = featb[(kb + bb) * 4096 + fidx];
                } else if (kb < 256) {
                    if (vh)
                        #pragma unroll
                        for (int bb = 0; bb < 4; ++bb) vals[j][bb] = hrb[(kb - 128 + bb) * 65536 + hidx];
                } else if (kb < 384) {
                    #pragma unroll
                    for (int bb = 0; bb < 4; ++bb) {
                        int cc = kb - 256 + bb;
                        float a = vh ? hrb[cc * 65536 + hidx] : 0.f;
                        vals[j][bb] = a - (v ? lrb[cc * 4096 + fidx] : 0.f);
                    }
                } else if (kb == 384) {
                    vals[j][0] = rel_y; vals[j][1] = rel_x;
                }
            }
            #pragma unroll
            for (int bb = 0; bb < 4; ++bb) vmax = fmaxf(vmax, fabsf(vals[j][bb]));
        }
        #pragma unroll
        for (int o = 16; o; o >>= 1) vmax = fmaxf(vmax, __shfl_xor_sync(0xffffffffu, vmax, o));
        vmax = fmaxf(vmax, 1e-20f);
        float inv = 32512.f / vmax;
        if (lane < 4) X0S[((size_t)mb * 4 + lane) * 128 + row] = vmax / 32512.f;

        #pragma unroll
        for (int j = 0; j < 4; ++j) {
            int c = lane + 32 * j;
            if (c >= 112) continue;
            uint32_t h = 0, l = 0;
            #pragma unroll
            for (int bb = 0; bb < 4; ++bb) {
                int x1, x0; qdig(vals[j][bb], inv, x1, x0);
                h |= ((uint32_t)(uint8_t)(int8_t)x1) << (8 * bb);
                l |= ((uint32_t)(uint8_t)(int8_t)x0) << (8 * bb);
            }
            X0I[((size_t)(mb * 2 + 0) * 128 + row) * 112 + c] = h;
            X0I[((size_t)(mb * 2 + 1) * 128 + row) * 112 + c] = l;
        }
    }
}

// ---------------- layer kernel ----------------
// smem: slot s = [A: 2 planes x 128 rows x 80B (64 data + pad)] + [W: 16KB]; 2 slots; misc @73728
constexpr int SLOT = 20480 + 16384;          // 36864
constexpr int MISC = 2 * SLOT;               // 73728
constexpr int SMEMSZ = MISC + 512 + 512 + 4096 + 1024 + 1024;  // 80896

template<int L>
__global__ __launch_bounds__(NTH, 1)
void layer_k(const float* __restrict__ bias, const float* __restrict__ w5g,
             const float* __restrict__ b5g, float* __restrict__ out, int mb0)
{
    constexpr int KC   = (L == 1) ? 7 : (L == 2) ? 16 : (L == 3) ? 8 : 4;
    constexpr int GIN  = (KC + 1) >> 1;
    constexpr int KB   = KC * 64;                       // input row bytes
    constexpr int NOUT = (L == 1) ? 1024 : (L == 2) ? 512 : (L == 3) ? 256 : 128;
    constexpr int NB   = NOUT / 128;

    const uint32_t* Xin = (L == 1) ? X0I : (L == 2) ? X1I : (L == 3) ? X2I : X3I;
    uint32_t*      Xout = (L == 1) ? X1I : (L == 2) ? X2I : X3I;
    const uint4*   Wb   = (L == 1) ? W1B : (L == 2) ? W2B : (L == 3) ? W3B : W4B;
    const float*   Sin  = (L == 1) ? X0S : (L == 2) ? X1S : (L == 3) ? X2S : X3S;
    float*         Sout = (L == 1) ? X1S : (L == 2) ? X2S : X3S;
    const float*   WS   = (L == 1) ? W1S : (L == 2) ? W2S : (L == 3) ? W3S : W4S;

    extern __shared__ uint8_t smem[];
    const int tid = threadIdx.x, lane = tid & 31, warp = tid >> 5;
    const int t4 = lane & 3, g = lane >> 2;
    const int nb = blockIdx.x, mb = blockIdx.y;
    const int wr = warp * 16;

    float*  sbias = (float*)(smem + MISC);
    float*  sws   = (float*)(smem + MISC + 512);
    float*  sxs   = (float*)(smem + MISC + 1024);
    float*  sw5   = (float*)(smem + MISC + 5120);
    float2* shead = (float2*)(smem + MISC + 6144);

    if (tid < 128) { sbias[tid] = bias[nb * 128 + tid]; sws[tid] = WS[nb * 128 + tid]; }
    for (int i = tid; i < GIN * 128; i += NTH) sxs[i] = Sin[(size_t)mb * GIN * 128 + i];
    if (L == 4) { if (tid < 256) sw5[tid] = w5g[tid]; }

    const uint32_t sb = smem_u32(smem);
    const uint8_t* gAbase = (const uint8_t*)Xin;
    const uint8_t* gWbase = (const uint8_t*)(Wb + (size_t)nb * KC * (NT * 2 * 32));

    auto stage = [&](int kc, int s) {
        uint32_t sA = sb + s * SLOT;
        #pragma unroll
        for (int i = 0; i < 4; ++i) {
            int t = tid + i * 256;                  // 0..1023
            int plane = t >> 9, rest = t & 511;
            int row = rest >> 2, seg = rest & 3;
            const uint8_t* src = gAbase + ((size_t)(mb * 2 + plane) * 128 + row) * KB + kc * 64 + seg * 16;
            cpa16(sA + plane * 10240 + row * 80 + seg * 16, src);
        }
        uint32_t sW = sA + 20480;
        const uint8_t* srcW = gWbase + (size_t)kc * 16384;
        #pragma unroll
        for (int i = 0; i < 4; ++i) {
            int t = tid + i * 256;
            cpa16(sW + t * 16, srcW + t * 16);
        }
    };

    int accH[NT][4], accM[NT][4];
    float accF[NT][4];
    #pragma unroll
    for (int nt = 0; nt < NT; ++nt)
        #pragma unroll
        for (int j = 0; j < 4; ++j) { accH[nt][j] = 0; accM[nt][j] = 0; accF[nt][j] = 0.f; }

    stage(0, 0);
    cpa_commit();

    #pragma unroll 1
    for (int kc = 0; kc < KC; ++kc) {
        const int s = kc & 1;
        if (kc + 1 < KC) { stage(kc + 1, s ^ 1); cpa_commit(); cpa_wait<1>(); }
        else             { cpa_wait<0>(); }
        __syncthreads();

        const uint32_t* sA = (const uint32_t*)(smem + s * SLOT);
        const uint4*    sW = (const uint4*)(smem + s * SLOT + 20480);

        #pragma unroll
        for (int tile = 0; tile < 2; ++tile) {
            uint32_t ah[4], al[4];
            int r0 = (wr + g) * 20 + tile * 8 + t4;
            int r1 = (wr + g + 8) * 20 + tile * 8 + t4;
            ah[0] = sA[r0]; ah[1] = sA[r1]; ah[2] = sA[r0 + 4]; ah[3] = sA[r1 + 4];
            const uint32_t* sAl = sA + 2560;
            al[0] = sAl[r0]; al[1] = sAl[r1]; al[2] = sAl[r0 + 4]; al[3] = sAl[r1 + 4];
            #pragma unroll
            for (int nt = 0; nt < NT; ++nt) {
                uint4 wv = sW[(nt * 2 + tile) * 32 + lane];
                mma_s8(accH[nt], ah, wv.x, wv.y);   // x1*w1
                mma_s8(accM[nt], ah, wv.z, wv.w);   // x1*w0
                mma_s8(accM[nt], al, wv.x, wv.y);   // x0*w1
            }
        }
        if ((kc & 1) || kc == KC - 1) {
            int grp = kc >> 1;
            float sxa = sxs[grp * 128 + wr + g];
            float sxb = sxs[grp * 128 + wr + g + 8];
            #pragma unroll
            for (int nt = 0; nt < NT; ++nt)
                #pragma unroll
                for (int j = 0; j < 4; ++j) {
                    float f = fmaf(65536.f, (float)accH[nt][j], 256.f * (float)accM[nt][j]);
                    accF[nt][j] = fmaf((j < 2) ? sxa : sxb, f, accF[nt][j]);
                    accH[nt][j] = 0; accM[nt][j] = 0;
                }
        }
        __syncthreads();
    }

    if (L != 4) {
        // pass 1: row maxes
        float rmA = 0.f, rmB = 0.f;
        #pragma unroll
        for (int nt = 0; nt < NT; ++nt)
            #pragma unroll
            for (int j = 0; j < 4; ++j) {
                int col = nt * 8 + t4 * 2 + (j & 1);
                float x = fmaxf(fmaf(accF[nt][j], sws[col], sbias[col]), 0.f);
                if (j < 2) rmA = fmaxf(rmA, x); else rmB = fmaxf(rmB, x);
            }
        rmA = fmaxf(rmA, __shfl_xor_sync(0xffffffffu, rmA, 1));
        rmA = fmaxf(rmA, __shfl_xor_sync(0xffffffffu, rmA, 2));
        rmB = fmaxf(rmB, __shfl_xor_sync(0xffffffffu, rmB, 1));
        rmB = fmaxf(rmB, __shfl_xor_sync(0xffffffffu, rmB, 2));
        rmA = fmaxf(rmA, 1e-20f); rmB = fmaxf(rmB, 1e-20f);
        float invA = 32512.f / rmA, invB = 32512.f / rmB;
        if (t4 == 0) {
            Sout[((size_t)mb * NB + nb) * 128 + wr + g]     = rmA / 32512.f;
            Sout[((size_t)mb * NB + nb) * 128 + wr + g + 8] = rmB / 32512.f;
        }
        // pass 2: quantize into smem staging (reuse slot area)
        uint8_t* dH = smem;
        uint8_t* dL = smem + 18432;
        #pragma unroll
        for (int nt = 0; nt < NT; ++nt)
            #pragma unroll
            for (int j = 0; j < 4; ++j) {
                int col = nt * 8 + t4 * 2 + (j & 1);
                int row = wr + g + ((j >> 1) ? 8 : 0);
                float x = fmaxf(fmaf(accF[nt][j], sws[col], sbias[col]), 0.f);
                int x1, x0; qdig(x, (j < 2) ? invA : invB, x1, x0);
                dH[row * 144 + col] = (uint8_t)(int8_t)x1;
                dL[row * 144 + col] = (uint8_t)(int8_t)x0;
            }
        __syncthreads();
        // coalesced copy to global image
        for (int t = tid; t < 2048; t += NTH) {
            int plane = t >> 10, r2 = t & 1023;
            int row = r2 >> 3, seg = r2 & 7;
            uint4 val = *(const uint4*)(smem + plane * 18432 + row * 144 + seg * 16);
            *(uint4*)((uint8_t*)Xout + ((size_t)(mb * 2 + plane) * 128 + row) * NOUT + nb * 128 + seg * 16) = val;
        }
    } else {
        // fused 128->2 head + branch softmax
        float p0a = 0.f, p1a = 0.f, p0b = 0.f, p1b = 0.f;
        #pragma unroll
        for (int nt = 0; nt < NT; ++nt)
            #pragma unroll
            for (int j = 0; j < 4; ++j) {
                int col = nt * 8 + t4 * 2 + (j & 1);
                float x = fmaxf(fmaf(accF[nt][j], sws[col], sbias[col]), 0.f);
                if (j < 2) { p0a += x * sw5[2 * col]; p1a += x * sw5[2 * col + 1]; }
                else       { p0b += x * sw5[2 * col]; p1b += x * sw5[2 * col + 1]; }
            }
        p0a += __shfl_xor_sync(0xffffffffu, p0a, 1); p0a += __shfl_xor_sync(0xffffffffu, p0a, 2);
        p1a += __shfl_xor_sync(0xffffffffu, p1a, 1); p1a += __shfl_xor_sync(0xffffffffu, p1a, 2);
        p0b += __shfl_xor_sync(0xffffffffu, p0b, 1); p0b += __shfl_xor_sync(0xffffffffu, p0b, 2);
        p1b += __shfl_xor_sync(0xffffffffu, p1b, 1); p1b += __shfl_xor_sync(0xffffffffu, p1b, 2);
        if (t4 == 0) {
            float b50 = b5g[0], b51 = b5g[1];
            shead[wr + g]     = make_float2(p0a + b50, p1a + b51);
            shead[wr + g + 8] = make_float2(p0b + b50, p1b + b51);
        }
        __syncthreads();
        if (tid < 32) {
            float2 r0 = shead[tid * 4 + 0], r1 = shead[tid * 4 + 1];
            float2 r2 = shead[tid * 4 + 2], r3 = shead[tid * 4 + 3];
            float m = fmaxf(fmaxf(r0.y, r1.y), fmaxf(r2.y, r3.y));
            float e0 = expf(r0.y - m), e1 = expf(r1.y - m);
            float e2 = expf(r2.y - m), e3 = expf(r3.y - m);
            out[(size_t)(mb0 + mb) * 32 + tid] =
                (r0.x * e0 + r1.x * e1 + r2.x * e2 + r3.x * e3) / (e0 + e1 + e2 + e3);
        }
    }
}

// ---------------- launch ----------------
extern "C" void kernel_launch(void* const* d_in, const int* in_sizes, int n_in,
                              void* d_out, int out_size) {
    const float* feat     = (const float*)d_in[0];
    const float* coord    = (const float*)d_in[1];
    const float* hr_guide = (const float*)d_in[2];
    const float* lr_guide = (const float*)d_in[3];
    const float* w1 = (const float*)d_in[4];
    const float* b1 = (const float*)d_in[5];
    const float* w2 = (const float*)d_in[6];
    const float* b2 = (const float*)d_in[7];
    const float* w3 = (const float*)d_in[8];
    const float* b3 = (const float*)d_in[9];
    const float* w4 = (const float*)d_in[10];
    const float* b4 = (const float*)d_in[11];
    const float* w5 = (const float*)d_in[12];
    const float* b5 = (const float*)d_in[13];
    float* out = (float*)d_out;

    cudaFuncSetAttribute(layer_k<1>, cudaFuncAttributeMaxDynamicSharedMemorySize, SMEMSZ);
    cudaFuncSetAttribute(layer_k<2>, cudaFuncAttributeMaxDynamicSharedMemorySize, SMEMSZ);
    cudaFuncSetAttribute(layer_k<3>, cudaFuncAttributeMaxDynamicSharedMemorySize, SMEMSZ);
    cudaFuncSetAttribute(layer_k<4>, cudaFuncAttributeMaxDynamicSharedMemorySize, SMEMSZ);

    // weight scales + digit blobs
    float *s1, *s2, *s3, *s4;
    cudaGetSymbolAddress((void**)&s1, W1S);
    cudaGetSymbolAddress((void**)&s2, W2S);
    cudaGetSymbolAddress((void**)&s3, W3S);
    cudaGetSymbolAddress((void**)&s4, W4S);
    colmax_k<<<(1024 + 255) / 256, 256>>>(w1, 386,  1024, s1);
    colmax_k<<<(512  + 255) / 256, 256>>>(w2, 1024, 512,  s2);
    colmax_k<<<(256  + 255) / 256, 256>>>(w3, 512,  256,  s3);
    colmax_k<<<(128  + 255) / 256, 256>>>(w4, 256,  128,  s4);
    prep_w<<<(8 * 7  * NT * 64 + 255) / 256, 256>>>(w1, s1, 386,  1024, 8, 7,  1);
    prep_w<<<(4 * 16 * NT * 64 + 255) / 256, 256>>>(w2, s2, 1024, 512,  4, 16, 2);
    prep_w<<<(2 * 8  * NT * 64 + 255) / 256, 256>>>(w3, s3, 512,  256,  2, 8,  3);
    prep_w<<<(1 * 4  * NT * 64 + 255) / 256, 256>>>(w4, s4, 256,  128,  1, 4,  4);

    for (int c = 0; c < MB / CH; ++c) {
        int mb0 = c * CH;
        gather_k<<<CH, NTH>>>(feat, coord, hr_guide, lr_guide, mb0);
        layer_k<1><<<dim3(8, CH), NTH, SMEMSZ>>>(b1, nullptr, nullptr, nullptr, mb0);
        layer_k<2><<<dim3(4, CH), NTH, SMEMSZ>>>(b2, nullptr, nullptr, nullptr, mb0);
        layer_k<3><<<dim3(2, CH), NTH, SMEMSZ>>>(b3, nullptr, nullptr, nullptr, mb0);
        layer_k<4><<<dim3(1, CH), NTH, SMEMSZ>>>(b4, w5, b5, out, mb0);
    }
}